// round 14
// baseline (speedup 1.0000x reference)
#include <cuda_runtime.h>
#include <cuda_fp16.h>
#include <cstdint>

#define HWSZ (512*512)
#define BATCH 4

// fp16 scratch (per-batch slice = 67MB, fits L2 for conv->attn reuse):
// g_y1h: pixel-major half2 channel-pairs [p][16]
// g_y2h: channel-major half [b][32][hw]
// g_y3h: channel-pair planes half2 [b][32cp][hw]
__device__ __align__(16) __half2 g_y1h[(size_t)BATCH*HWSZ*16];
__device__ __align__(16) __half  g_y2h[(size_t)BATCH*32*HWSZ];
__device__ __align__(16) __half2 g_y3h[(size_t)BATCH*32*HWSZ];
__device__ __align__(16) __half  g_wA[128*64];   // pre-swizzled fp16 weights
__device__ float g_bias[128];

__device__ __forceinline__ unsigned swz(unsigned b){ return b ^ ((b >> 3) & 0x70); }

__global__ void pack_weights(const float* __restrict__ w1, const float* __restrict__ b1,
                             const float* __restrict__ w2, const float* __restrict__ b2,
                             const float* __restrict__ w3, const float* __restrict__ b3){
    int idx = blockIdx.x*256 + threadIdx.x;          // grid 32 x 256 = 8192
    int o = idx >> 6, c = idx & 63;
    float v = (o < 32) ? w1[o*64 + c] : (o < 64) ? w2[(o-32)*64 + c] : w3[(o-64)*64 + c];
    g_wA[swz((unsigned)o*128u + (unsigned)c*2u) >> 1] = __float2half(v);
    if (blockIdx.x == 0 && threadIdx.x < 128){
        int t = threadIdx.x;
        g_bias[t] = (t < 32) ? b1[t] : (t < 64) ? b2[t-32] : b3[t-64];
    }
}

// ---------------------------------------------------------------------------
// conv_mma: EXACT R11 structure; batch passed as parameter (grid = 2048).
// smem: ws @0 (16KB verbatim copy), xs @16384 (16KB); Tbuf overlays. 33792 B.
// ---------------------------------------------------------------------------
#define XS_OFF 16384
#define CONV_SMEM 33792

#define MMA16816(D, A, B) \
    asm volatile("mma.sync.aligned.m16n8k16.row.col.f32.f16.f16.f32 " \
        "{%0,%1,%2,%3}, {%4,%5,%6,%7}, {%8,%9}, {%0,%1,%2,%3};" \
        : "+f"((D)[0]), "+f"((D)[1]), "+f"((D)[2]), "+f"((D)[3]) \
        : "r"((A)[0]), "r"((A)[1]), "r"((A)[2]), "r"((A)[3]), "r"((B)[0]), "r"((B)[1]))

__global__ void __launch_bounds__(256) conv_mma(const float* __restrict__ x, int b){
    extern __shared__ char smem[];
    int t = threadIdx.x, lane = t & 31, wid = t >> 5;
    int g = lane >> 2, tg = lane & 3;

    int hw0 = blockIdx.x << 7;
    const float* xb = x + ((size_t)b * 64) * HWSZ + hw0;

    {
        const uint4* s = reinterpret_cast<const uint4*>(g_wA);
        uint4* d = reinterpret_cast<uint4*>(smem);
        #pragma unroll
        for (int i = 0; i < 4; i++) d[t + 256*i] = s[t + 256*i];
    }
    {
        int px = t >> 1, cb = (t & 1) * 32;
        #pragma unroll
        for (int cq = 0; cq < 8; cq++){
            int c = cb + cq*4;
            __half2 h0 = __floats2half2_rn(xb[(size_t)c*HWSZ + px],     xb[(size_t)(c+1)*HWSZ + px]);
            __half2 h1 = __floats2half2_rn(xb[(size_t)(c+2)*HWSZ + px], xb[(size_t)(c+3)*HWSZ + px]);
            uint2 pkt;
            pkt.x = *reinterpret_cast<uint32_t*>(&h0);
            pkt.y = *reinterpret_cast<uint32_t*>(&h1);
            *reinterpret_cast<uint2*>(smem + XS_OFF + swz((unsigned)px*128u + (unsigned)c*2u)) = pkt;
        }
    }
    __syncthreads();

    int m0 = (wid & 3) * 32, n0 = (wid >> 2) * 64;

    float d[2][8][4];
    #pragma unroll
    for (int mt = 0; mt < 2; mt++){
        float blo = g_bias[m0 + mt*16 + g];
        float bhi = g_bias[m0 + mt*16 + g + 8];
        #pragma unroll
        for (int nt = 0; nt < 8; nt++){
            d[mt][nt][0] = blo; d[mt][nt][1] = blo;
            d[mt][nt][2] = bhi; d[mt][nt][3] = bhi;
        }
    }

    const uint32_t* wsv = reinterpret_cast<const uint32_t*>(smem);
    const uint32_t* xsv = reinterpret_cast<const uint32_t*>(smem + XS_OFF);

    #pragma unroll
    for (int ks = 0; ks < 4; ks++){
        uint32_t a[2][4];
        #pragma unroll
        for (int mt = 0; mt < 2; mt++){
            unsigned r0 = (unsigned)(m0 + mt*16 + g);
            unsigned c0 = (unsigned)(ks*32 + tg*4);
            a[mt][0] = wsv[swz(r0*128u + c0) >> 2];
            a[mt][1] = wsv[swz((r0+8)*128u + c0) >> 2];
            a[mt][2] = wsv[swz(r0*128u + c0 + 16) >> 2];
            a[mt][3] = wsv[swz((r0+8)*128u + c0 + 16) >> 2];
        }
        #pragma unroll
        for (int nt = 0; nt < 8; nt++){
            unsigned pr = (unsigned)(n0 + nt*8 + g);
            unsigned bb = pr*128u + (unsigned)(ks*32 + tg*4);
            uint32_t bfrag[2];
            bfrag[0] = xsv[swz(bb) >> 2];
            bfrag[1] = xsv[swz(bb + 16) >> 2];
            MMA16816(d[0][nt], a[0], bfrag);
            MMA16816(d[1][nt], a[1], bfrag);
        }
    }
    __syncthreads();

    float* Tb = reinterpret_cast<float*>(smem);
    #pragma unroll
    for (int ph = 0; ph < 2; ph++){
        if ((wid >> 2) == ph){
            #pragma unroll
            for (int mt = 0; mt < 2; mt++){
                int ch = m0 + mt*16 + g;
                #pragma unroll
                for (int nt = 0; nt < 8; nt++){
                    int px = nt*8 + 2*tg;
                    *reinterpret_cast<float2*>(&Tb[ch*66 + px])     = make_float2(d[mt][nt][0], d[mt][nt][1]);
                    *reinterpret_cast<float2*>(&Tb[(ch+8)*66 + px]) = make_float2(d[mt][nt][2], d[mt][nt][3]);
                }
            }
        }
        __syncthreads();
        int px0 = hw0 + ph*64;
        #pragma unroll
        for (int i = 0; i < 4; i++){       // y1h: pixel-major half2 pairs
            int e = t + 256*i;
            int cp = e & 15, px = e >> 4;
            g_y1h[((size_t)b*HWSZ + px0 + px)*16 + cp] =
                __floats2half2_rn(Tb[(2*cp)*66 + px], Tb[(2*cp+1)*66 + px]);
        }
        #pragma unroll
        for (int i = 0; i < 8; i++){       // y2h: channel-major half
            int e = t + 256*i;
            int c = e >> 6, px = e & 63;
            g_y2h[((size_t)b*32 + c)*HWSZ + px0 + px] = __float2half(Tb[(32+c)*66 + px]);
        }
        #pragma unroll
        for (int i = 0; i < 8; i++){       // y3h: channel-pair planes half2
            int e = t + 256*i;
            int cp = e >> 6, px = e & 63;
            g_y3h[((size_t)b*32 + cp)*HWSZ + px0 + px] =
                __floats2half2_rn(Tb[(64+2*cp)*66 + px], Tb[(64+2*cp+1)*66 + px]);
        }
        __syncthreads();
    }
}

// ---------------------------------------------------------------------------
// attn_tiled: EXACT R11 structure; batch passed as parameter (grid 16x64).
// ---------------------------------------------------------------------------
#define PITCH 341
#define HALO  340

__global__ void __launch_bounds__(256) attn_tiled(const float* __restrict__ x,
                                                  const float* __restrict__ gamma,
                                                  float* __restrict__ out, int b){
    __shared__ uint32_t sm1[16*PITCH];
    __shared__ uint32_t sm3[8*PITCH];
    int t = threadIdx.x, lane = t & 31, wi = t >> 5;
    int h0 = blockIdx.y*8, w0 = blockIdx.x*32;
    size_t pb = (size_t)b << 18;

    {
        const uint32_t* y1v = reinterpret_cast<const uint32_t*>(g_y1h);
        for (int e = t; e < HALO*16; e += 256){
            int hp = e >> 4, cp = e & 15;
            int hr = hp / 34, hc = hp - hr*34;
            int nh = min(max(h0 + hr - 1, 0), 511);
            int nw = min(max(w0 + hc - 1, 0), 511);
            sm1[cp*PITCH + hp] = y1v[(pb + (size_t)((nh<<9) + nw))*16 + cp];
        }
    }
    __syncthreads();

    int hbase = (wi+1)*34 + lane + 1;
    float av[9];
    {
        float acct[9];
        #pragma unroll
        for (int n = 0; n < 9; n++) acct[n] = 0.f;
        const __half* x2p = g_y2h + ((size_t)b*32)*HWSZ + (size_t)(((h0+wi)<<9) + w0 + lane);
        #pragma unroll 4
        for (int cp = 0; cp < 16; cp++){
            float xa = 0.5f * __half2float(__ldg(x2p + (size_t)(2*cp)*HWSZ));
            float xc = 0.5f * __half2float(__ldg(x2p + (size_t)(2*cp+1)*HWSZ));
            #pragma unroll
            for (int n = 0; n < 9; n++){
                const int D = (n/3 - 1)*34 + (n%3 - 1);
                float2 f = __half22float2(*reinterpret_cast<const __half2*>(&sm1[cp*PITCH + hbase + D]));
                float t0, t1;
                asm("tanh.approx.f32 %0, %1;" : "=f"(t0) : "f"(f.x * xa));
                asm("tanh.approx.f32 %0, %1;" : "=f"(t1) : "f"(f.y * xc));
                acct[n] += t0 + t1;
            }
        }
        #pragma unroll
        for (int n = 0; n < 9; n++){
            int nh = h0 + wi + n/3 - 1, nw = w0 + lane + n%3 - 1;
            bool ok = ((unsigned)nh < 512u) && ((unsigned)nw < 512u);
            av[n] = ok ? fmaf(0.5f, acct[n], 16.0f) : 0.f;
        }
    }

    float gm = __ldg(gamma);
    int hw = ((h0+wi)<<9) + w0 + lane;
    #pragma unroll 1
    for (int ch = 0; ch < 4; ch++){
        __syncthreads();
        {
            const uint32_t* src = reinterpret_cast<const uint32_t*>(
                g_y3h + ((size_t)(b*32 + ch*8 + wi))*HWSZ);
            for (int hp = lane; hp < HALO; hp += 32){
                int hr = hp / 34, hc = hp - hr*34;
                int nh = min(max(h0 + hr - 1, 0), 511);
                int nw = min(max(w0 + hc - 1, 0), 511);
                sm3[wi*PITCH + hp] = src[(nh<<9) + nw];
            }
        }
        __syncthreads();
        size_t obase = ((size_t)(b*64 + ch*16))*HWSZ + hw;
        #pragma unroll
        for (int cpl = 0; cpl < 8; cpl++){
            float a0 = 0.f, a1 = 0.f;
            #pragma unroll
            for (int n = 0; n < 9; n++){
                const int D = (n/3 - 1)*34 + (n%3 - 1);
                float2 f = __half22float2(*reinterpret_cast<const __half2*>(&sm3[cpl*PITCH + hbase + D]));
                a0 = fmaf(f.x, av[n], a0);
                a1 = fmaf(f.y, av[n], a1);
            }
            size_t o0 = obase + (size_t)(2*cpl)*HWSZ;
            size_t o1 = o0 + HWSZ;
            out[o0] = x[o0] + gm * a0;
            out[o1] = x[o1] + gm * a1;
        }
    }
}

extern "C" void kernel_launch(void* const* d_in, const int* in_sizes, int n_in,
                              void* d_out, int out_size){
    const float* x     = (const float*)d_in[0];
    const float* w1    = (const float*)d_in[1];
    const float* b1    = (const float*)d_in[2];
    const float* w2    = (const float*)d_in[3];
    const float* b2    = (const float*)d_in[4];
    const float* w3    = (const float*)d_in[5];
    const float* b3    = (const float*)d_in[6];
    const float* gamma = (const float*)d_in[7];
    float* out = (float*)d_out;

    cudaFuncSetAttribute(conv_mma, cudaFuncAttributeMaxDynamicSharedMemorySize, CONV_SMEM);
    pack_weights<<<32, 256>>>(w1, b1, w2, b2, w3, b3);
    // interleave per batch: attn(b) reads conv(b)'s 67MB scratch while it's L2-hot
    for (int b = 0; b < BATCH; b++){
        conv_mma<<<HWSZ/128, 256, CONV_SMEM>>>(x, b);
        attn_tiled<<<dim3(16, 64, 1), 256>>>(x, gamma, out, b);
    }
}

// round 15
// speedup vs baseline: 1.2553x; 1.2553x over previous
#include <cuda_runtime.h>
#include <cuda_fp16.h>
#include <cstdint>

#define HWSZ (512*512)
#define BATCH 4

// fp16 scratch:
// g_y1h: pixel-major half2 channel-pairs [p][16]
// g_y2h: channel-major half [b][32][hw]
// g_y3h: channel-pair planes half2 [b][32cp][hw]
__device__ __align__(16) __half2 g_y1h[(size_t)BATCH*HWSZ*16];
__device__ __align__(16) __half  g_y2h[(size_t)BATCH*32*HWSZ];
__device__ __align__(16) __half2 g_y3h[(size_t)BATCH*32*HWSZ];
__device__ __align__(16) __half  g_wA[128*64];   // pre-swizzled fp16 weights
__device__ float g_bias[128];

__device__ __forceinline__ unsigned swz(unsigned b){ return b ^ ((b >> 3) & 0x70); }

__global__ void pack_weights(const float* __restrict__ w1, const float* __restrict__ b1,
                             const float* __restrict__ w2, const float* __restrict__ b2,
                             const float* __restrict__ w3, const float* __restrict__ b3){
    int idx = blockIdx.x*256 + threadIdx.x;          // grid 32 x 256 = 8192
    int o = idx >> 6, c = idx & 63;
    float v = (o < 32) ? w1[o*64 + c] : (o < 64) ? w2[(o-32)*64 + c] : w3[(o-64)*64 + c];
    g_wA[swz((unsigned)o*128u + (unsigned)c*2u) >> 1] = __float2half(v);
    if (blockIdx.x == 0 && threadIdx.x < 128){
        int t = threadIdx.x;
        g_bias[t] = (t < 32) ? b1[t] : (t < 64) ? b2[t-32] : b3[t-64];
    }
}

// ---------------------------------------------------------------------------
// conv_mma: R11 structure; staging STS rotated per-lane for conflict-free
// crossbar phases. smem: ws @0 (16KB), xs @16384 (16KB); Tbuf overlays.
// ---------------------------------------------------------------------------
#define XS_OFF 16384
#define CONV_SMEM 33792

#define MMA16816(D, A, B) \
    asm volatile("mma.sync.aligned.m16n8k16.row.col.f32.f16.f16.f32 " \
        "{%0,%1,%2,%3}, {%4,%5,%6,%7}, {%8,%9}, {%0,%1,%2,%3};" \
        : "+f"((D)[0]), "+f"((D)[1]), "+f"((D)[2]), "+f"((D)[3]) \
        : "r"((A)[0]), "r"((A)[1]), "r"((A)[2]), "r"((A)[3]), "r"((B)[0]), "r"((B)[1]))

__global__ void __launch_bounds__(256, 2) conv_mma(const float* __restrict__ x){
    extern __shared__ char smem[];
    int t = threadIdx.x, lane = t & 31, wid = t >> 5;
    int g = lane >> 2, tg = lane & 3;

    int tile = blockIdx.x;
    int b = tile >> 11;
    int hw0 = (tile & 2047) << 7;
    const float* xb = x + ((size_t)b * 64) * HWSZ + hw0;

    // weights: verbatim 16KB copy of pre-swizzled tile
    {
        const uint4* s = reinterpret_cast<const uint4*>(g_wA);
        uint4* d = reinterpret_cast<uint4*>(smem);
        #pragma unroll
        for (int i = 0; i < 4; i++) d[t + 256*i] = s[t + 256*i];
    }
    // stage x: row = px (128B = 64 ch fp16), swizzled.
    // Load all 8 packets (coalesced LDG unchanged), then store with per-lane
    // rotation cq = (i+px)&7 -> each STS phase hits 16 distinct bank-pairs.
    {
        int px = t >> 1, cb = (t & 1) * 32;
        uint2 pkt[8];
        #pragma unroll
        for (int cq = 0; cq < 8; cq++){
            int c = cb + cq*4;
            __half2 h0 = __floats2half2_rn(xb[(size_t)c*HWSZ + px],     xb[(size_t)(c+1)*HWSZ + px]);
            __half2 h1 = __floats2half2_rn(xb[(size_t)(c+2)*HWSZ + px], xb[(size_t)(c+3)*HWSZ + px]);
            pkt[cq].x = *reinterpret_cast<uint32_t*>(&h0);
            pkt[cq].y = *reinterpret_cast<uint32_t*>(&h1);
        }
        #pragma unroll
        for (int i = 0; i < 8; i++){
            int cq = (i + px) & 7;
            *reinterpret_cast<uint2*>(smem + XS_OFF +
                swz((unsigned)px*128u + (unsigned)(cb + cq*4)*2u)) = pkt[cq];
        }
    }
    __syncthreads();

    int m0 = (wid & 3) * 32, n0 = (wid >> 2) * 64;

    float d[2][8][4];
    #pragma unroll
    for (int mt = 0; mt < 2; mt++){
        float blo = g_bias[m0 + mt*16 + g];
        float bhi = g_bias[m0 + mt*16 + g + 8];
        #pragma unroll
        for (int nt = 0; nt < 8; nt++){
            d[mt][nt][0] = blo; d[mt][nt][1] = blo;
            d[mt][nt][2] = bhi; d[mt][nt][3] = bhi;
        }
    }

    const uint32_t* wsv = reinterpret_cast<const uint32_t*>(smem);
    const uint32_t* xsv = reinterpret_cast<const uint32_t*>(smem + XS_OFF);

    #pragma unroll
    for (int ks = 0; ks < 4; ks++){
        uint32_t a[2][4];
        #pragma unroll
        for (int mt = 0; mt < 2; mt++){
            unsigned r0 = (unsigned)(m0 + mt*16 + g);
            unsigned c0 = (unsigned)(ks*32 + tg*4);
            a[mt][0] = wsv[swz(r0*128u + c0) >> 2];
            a[mt][1] = wsv[swz((r0+8)*128u + c0) >> 2];
            a[mt][2] = wsv[swz(r0*128u + c0 + 16) >> 2];
            a[mt][3] = wsv[swz((r0+8)*128u + c0 + 16) >> 2];
        }
        #pragma unroll
        for (int nt = 0; nt < 8; nt++){
            unsigned pr = (unsigned)(n0 + nt*8 + g);
            unsigned bb = pr*128u + (unsigned)(ks*32 + tg*4);
            uint32_t bfrag[2];
            bfrag[0] = xsv[swz(bb) >> 2];
            bfrag[1] = xsv[swz(bb + 16) >> 2];
            MMA16816(d[0][nt], a[0], bfrag);
            MMA16816(d[1][nt], a[1], bfrag);
        }
    }
    __syncthreads();

    // epilogue: two px-halves through Tbuf[128][66], fp16 outputs
    float* Tb = reinterpret_cast<float*>(smem);
    #pragma unroll
    for (int ph = 0; ph < 2; ph++){
        if ((wid >> 2) == ph){
            #pragma unroll
            for (int mt = 0; mt < 2; mt++){
                int ch = m0 + mt*16 + g;
                #pragma unroll
                for (int nt = 0; nt < 8; nt++){
                    int px = nt*8 + 2*tg;
                    *reinterpret_cast<float2*>(&Tb[ch*66 + px])     = make_float2(d[mt][nt][0], d[mt][nt][1]);
                    *reinterpret_cast<float2*>(&Tb[(ch+8)*66 + px]) = make_float2(d[mt][nt][2], d[mt][nt][3]);
                }
            }
        }
        __syncthreads();
        int px0 = hw0 + ph*64;
        #pragma unroll
        for (int i = 0; i < 4; i++){       // y1h: pixel-major half2 pairs
            int e = t + 256*i;
            int cp = e & 15, px = e >> 4;
            g_y1h[((size_t)b*HWSZ + px0 + px)*16 + cp] =
                __floats2half2_rn(Tb[(2*cp)*66 + px], Tb[(2*cp+1)*66 + px]);
        }
        #pragma unroll
        for (int i = 0; i < 8; i++){       // y2h: channel-major half
            int e = t + 256*i;
            int c = e >> 6, px = e & 63;
            g_y2h[((size_t)b*32 + c)*HWSZ + px0 + px] = __float2half(Tb[(32+c)*66 + px]);
        }
        #pragma unroll
        for (int i = 0; i < 8; i++){       // y3h: channel-pair planes half2
            int e = t + 256*i;
            int cp = e >> 6, px = e & 63;
            g_y3h[((size_t)b*32 + cp)*HWSZ + px0 + px] =
                __floats2half2_rn(Tb[(64+2*cp)*66 + px], Tb[(64+2*cp+1)*66 + px]);
        }
        __syncthreads();
    }
}

// ---------------------------------------------------------------------------
// attn_tiled: EXACT Round-11 version (best known).
// ---------------------------------------------------------------------------
#define PITCH 341
#define HALO  340

__global__ void __launch_bounds__(256) attn_tiled(const float* __restrict__ x,
                                                  const float* __restrict__ gamma,
                                                  float* __restrict__ out){
    __shared__ uint32_t sm1[16*PITCH];
    __shared__ uint32_t sm3[8*PITCH];
    int t = threadIdx.x, lane = t & 31, wi = t >> 5;
    int b = blockIdx.z, h0 = blockIdx.y*8, w0 = blockIdx.x*32;
    size_t pb = (size_t)b << 18;

    {
        const uint32_t* y1v = reinterpret_cast<const uint32_t*>(g_y1h);
        for (int e = t; e < HALO*16; e += 256){
            int hp = e >> 4, cp = e & 15;
            int hr = hp / 34, hc = hp - hr*34;
            int nh = min(max(h0 + hr - 1, 0), 511);
            int nw = min(max(w0 + hc - 1, 0), 511);
            sm1[cp*PITCH + hp] = y1v[(pb + (size_t)((nh<<9) + nw))*16 + cp];
        }
    }
    __syncthreads();

    int hbase = (wi+1)*34 + lane + 1;
    float av[9];
    {
        float acct[9];
        #pragma unroll
        for (int n = 0; n < 9; n++) acct[n] = 0.f;
        const __half* x2p = g_y2h + ((size_t)b*32)*HWSZ + (size_t)(((h0+wi)<<9) + w0 + lane);
        #pragma unroll 4
        for (int cp = 0; cp < 16; cp++){
            float xa = 0.5f * __half2float(__ldg(x2p + (size_t)(2*cp)*HWSZ));
            float xc = 0.5f * __half2float(__ldg(x2p + (size_t)(2*cp+1)*HWSZ));
            #pragma unroll
            for (int n = 0; n < 9; n++){
                const int D = (n/3 - 1)*34 + (n%3 - 1);
                float2 f = __half22float2(*reinterpret_cast<const __half2*>(&sm1[cp*PITCH + hbase + D]));
                float t0, t1;
                asm("tanh.approx.f32 %0, %1;" : "=f"(t0) : "f"(f.x * xa));
                asm("tanh.approx.f32 %0, %1;" : "=f"(t1) : "f"(f.y * xc));
                acct[n] += t0 + t1;
            }
        }
        #pragma unroll
        for (int n = 0; n < 9; n++){
            int nh = h0 + wi + n/3 - 1, nw = w0 + lane + n%3 - 1;
            bool ok = ((unsigned)nh < 512u) && ((unsigned)nw < 512u);
            av[n] = ok ? fmaf(0.5f, acct[n], 16.0f) : 0.f;
        }
    }

    float gm = __ldg(gamma);
    int hw = ((h0+wi)<<9) + w0 + lane;
    #pragma unroll 1
    for (int ch = 0; ch < 4; ch++){
        __syncthreads();
        {
            const uint32_t* src = reinterpret_cast<const uint32_t*>(
                g_y3h + ((size_t)(b*32 + ch*8 + wi))*HWSZ);
            for (int hp = lane; hp < HALO; hp += 32){
                int hr = hp / 34, hc = hp - hr*34;
                int nh = min(max(h0 + hr - 1, 0), 511);
                int nw = min(max(w0 + hc - 1, 0), 511);
                sm3[wi*PITCH + hp] = src[(nh<<9) + nw];
            }
        }
        __syncthreads();
        size_t obase = ((size_t)(b*64 + ch*16))*HWSZ + hw;
        #pragma unroll
        for (int cpl = 0; cpl < 8; cpl++){
            float a0 = 0.f, a1 = 0.f;
            #pragma unroll
            for (int n = 0; n < 9; n++){
                const int D = (n/3 - 1)*34 + (n%3 - 1);
                float2 f = __half22float2(*reinterpret_cast<const __half2*>(&sm3[cpl*PITCH + hbase + D]));
                a0 = fmaf(f.x, av[n], a0);
                a1 = fmaf(f.y, av[n], a1);
            }
            size_t o0 = obase + (size_t)(2*cpl)*HWSZ;
            size_t o1 = o0 + HWSZ;
            out[o0] = x[o0] + gm * a0;
            out[o1] = x[o1] + gm * a1;
        }
    }
}

extern "C" void kernel_launch(void* const* d_in, const int* in_sizes, int n_in,
                              void* d_out, int out_size){
    const float* x     = (const float*)d_in[0];
    const float* w1    = (const float*)d_in[1];
    const float* b1    = (const float*)d_in[2];
    const float* w2    = (const float*)d_in[3];
    const float* b2    = (const float*)d_in[4];
    const float* w3    = (const float*)d_in[5];
    const float* b3    = (const float*)d_in[6];
    const float* gamma = (const float*)d_in[7];
    float* out = (float*)d_out;

    cudaFuncSetAttribute(conv_mma, cudaFuncAttributeMaxDynamicSharedMemorySize, CONV_SMEM);
    pack_weights<<<32, 256>>>(w1, b1, w2, b2, w3, b3);
    conv_mma<<<(BATCH*HWSZ)/128, 256, CONV_SMEM>>>(x);
    attn_tiled<<<dim3(16, 64, BATCH), 256>>>(x, gamma, out);
}

// round 16
// speedup vs baseline: 1.3033x; 1.0383x over previous
#include <cuda_runtime.h>
#include <cuda_fp16.h>
#include <cstdint>

#define HWSZ (512*512)
#define BATCH 4

// fp16 scratch:
// g_y1h: pixel-major half2 channel-pairs [p][16]
// g_y2h: channel-major half [b][32][hw]
// g_y3h: channel-pair planes half2 [b][32cp][hw]
__device__ __align__(16) __half2 g_y1h[(size_t)BATCH*HWSZ*16];
__device__ __align__(16) __half  g_y2h[(size_t)BATCH*32*HWSZ];
__device__ __align__(16) __half2 g_y3h[(size_t)BATCH*32*HWSZ];
__device__ __align__(16) __half  g_wA[128*64];   // pre-swizzled fp16 weights
__device__ float g_bias[128];

__device__ __forceinline__ unsigned swz(unsigned b){ return b ^ ((b >> 3) & 0x70); }

__global__ void pack_weights(const float* __restrict__ w1, const float* __restrict__ b1,
                             const float* __restrict__ w2, const float* __restrict__ b2,
                             const float* __restrict__ w3, const float* __restrict__ b3){
    int idx = blockIdx.x*256 + threadIdx.x;          // grid 32 x 256 = 8192
    int o = idx >> 6, c = idx & 63;
    float v = (o < 32) ? w1[o*64 + c] : (o < 64) ? w2[(o-32)*64 + c] : w3[(o-64)*64 + c];
    g_wA[swz((unsigned)o*128u + (unsigned)c*2u) >> 1] = __float2half(v);
    if (blockIdx.x == 0 && threadIdx.x < 128){
        int t = threadIdx.x;
        g_bias[t] = (t < 32) ? b1[t] : (t < 64) ? b2[t-32] : b3[t-64];
    }
}

// ---------------------------------------------------------------------------
// conv_mma: R11 math; staging & epilogue re-vectorized (wide LDG/STS/STG).
// smem: ws @0 (16KB), xs @16384 (16KB); Tbuf float[128][66] overlays.
// ---------------------------------------------------------------------------
#define XS_OFF 16384
#define CONV_SMEM 33792

#define MMA16816(D, A, B) \
    asm volatile("mma.sync.aligned.m16n8k16.row.col.f32.f16.f16.f32 " \
        "{%0,%1,%2,%3}, {%4,%5,%6,%7}, {%8,%9}, {%0,%1,%2,%3};" \
        : "+f"((D)[0]), "+f"((D)[1]), "+f"((D)[2]), "+f"((D)[3]) \
        : "r"((A)[0]), "r"((A)[1]), "r"((A)[2]), "r"((A)[3]), "r"((B)[0]), "r"((B)[1]))

__global__ void __launch_bounds__(256, 2) conv_mma(const float* __restrict__ x){
    extern __shared__ char smem[];
    int t = threadIdx.x, lane = t & 31, wid = t >> 5;
    int g = lane >> 2, tg = lane & 3;

    int tile = blockIdx.x;
    int b = tile >> 11;
    int hw0 = (tile & 2047) << 7;
    const float* xb = x + ((size_t)b * 64) * HWSZ + hw0;

    // weights: verbatim 16KB copy of pre-swizzled tile
    {
        const uint4* s = reinterpret_cast<const uint4*>(g_wA);
        uint4* d = reinterpret_cast<uint4*>(smem);
        #pragma unroll
        for (int i = 0; i < 4; i++) d[t + 256*i] = s[t + 256*i];
    }
    // stage x: thread owns px pair (p0, p0+1) x 16 channels.
    // 16 coalesced LDG.64 (256B/warp/instr) -> F2FP -> PRMT repack -> 4 STS.128.
    {
        int p0 = (t & 63) * 2;
        int cb = (t >> 6) * 16;
        uint32_t h[16];
        #pragma unroll
        for (int i = 0; i < 16; i++){
            float2 v = *reinterpret_cast<const float2*>(xb + (size_t)(cb + i)*HWSZ + p0);
            __half2 hh = __floats2half2_rn(v.x, v.y);     // (px p0, px p0+1) of channel cb+i
            h[i] = *reinterpret_cast<uint32_t*>(&hh);
        }
        uint4 E0, E1;                                     // channel-contiguous per px
        uint32_t e0[8], e1[8];
        #pragma unroll
        for (int j = 0; j < 8; j++){
            e0[j] = __byte_perm(h[2*j], h[2*j+1], 0x5410);  // (ch 2j, ch 2j+1) @ px p0
            e1[j] = __byte_perm(h[2*j], h[2*j+1], 0x7632);  // @ px p0+1
        }
        E0 = make_uint4(e0[0], e0[1], e0[2], e0[3]);
        *reinterpret_cast<uint4*>(smem + XS_OFF + swz((unsigned)p0*128u + (unsigned)cb*2u)) = E0;
        E0 = make_uint4(e0[4], e0[5], e0[6], e0[7]);
        *reinterpret_cast<uint4*>(smem + XS_OFF + swz((unsigned)p0*128u + (unsigned)cb*2u + 16u)) = E0;
        E1 = make_uint4(e1[0], e1[1], e1[2], e1[3]);
        *reinterpret_cast<uint4*>(smem + XS_OFF + swz((unsigned)(p0+1)*128u + (unsigned)cb*2u)) = E1;
        E1 = make_uint4(e1[4], e1[5], e1[6], e1[7]);
        *reinterpret_cast<uint4*>(smem + XS_OFF + swz((unsigned)(p0+1)*128u + (unsigned)cb*2u + 16u)) = E1;
    }
    __syncthreads();

    int m0 = (wid & 3) * 32, n0 = (wid >> 2) * 64;

    float d[2][8][4];
    #pragma unroll
    for (int mt = 0; mt < 2; mt++){
        float blo = g_bias[m0 + mt*16 + g];
        float bhi = g_bias[m0 + mt*16 + g + 8];
        #pragma unroll
        for (int nt = 0; nt < 8; nt++){
            d[mt][nt][0] = blo; d[mt][nt][1] = blo;
            d[mt][nt][2] = bhi; d[mt][nt][3] = bhi;
        }
    }

    const uint32_t* wsv = reinterpret_cast<const uint32_t*>(smem);
    const uint32_t* xsv = reinterpret_cast<const uint32_t*>(smem + XS_OFF);

    #pragma unroll
    for (int ks = 0; ks < 4; ks++){
        uint32_t a[2][4];
        #pragma unroll
        for (int mt = 0; mt < 2; mt++){
            unsigned r0 = (unsigned)(m0 + mt*16 + g);
            unsigned c0 = (unsigned)(ks*32 + tg*4);
            a[mt][0] = wsv[swz(r0*128u + c0) >> 2];
            a[mt][1] = wsv[swz((r0+8)*128u + c0) >> 2];
            a[mt][2] = wsv[swz(r0*128u + c0 + 16) >> 2];
            a[mt][3] = wsv[swz((r0+8)*128u + c0 + 16) >> 2];
        }
        #pragma unroll
        for (int nt = 0; nt < 8; nt++){
            unsigned pr = (unsigned)(n0 + nt*8 + g);
            unsigned bb = pr*128u + (unsigned)(ks*32 + tg*4);
            uint32_t bfrag[2];
            bfrag[0] = xsv[swz(bb) >> 2];
            bfrag[1] = xsv[swz(bb + 16) >> 2];
            MMA16816(d[0][nt], a[0], bfrag);
            MMA16816(d[1][nt], a[1], bfrag);
        }
    }
    __syncthreads();

    // epilogue: two px-halves through Tbuf[128][66]; wide fp16 stores.
    float* Tb = reinterpret_cast<float*>(smem);
    #pragma unroll
    for (int ph = 0; ph < 2; ph++){
        if ((wid >> 2) == ph){
            #pragma unroll
            for (int mt = 0; mt < 2; mt++){
                int ch = m0 + mt*16 + g;
                #pragma unroll
                for (int nt = 0; nt < 8; nt++){
                    int px = nt*8 + 2*tg;
                    *reinterpret_cast<float2*>(&Tb[ch*66 + px])     = make_float2(d[mt][nt][0], d[mt][nt][1]);
                    *reinterpret_cast<float2*>(&Tb[(ch+8)*66 + px]) = make_float2(d[mt][nt][2], d[mt][nt][3]);
                }
            }
        }
        __syncthreads();
        int px0 = hw0 + ph*64;
        {   // y1h: 4 consecutive cp per thread -> 1 STG.128
            int cpg = t & 3, px = t >> 2;               // px 0..63, cp 4*cpg..+3
            uint32_t e[4];
            #pragma unroll
            for (int k = 0; k < 4; k++){
                int cp = cpg*4 + k;
                __half2 hh = __floats2half2_rn(Tb[(2*cp)*66 + px], Tb[(2*cp+1)*66 + px]);
                e[k] = *reinterpret_cast<uint32_t*>(&hh);
            }
            *reinterpret_cast<uint4*>(&g_y1h[((size_t)b*HWSZ + px0 + px)*16 + cpg*4]) =
                make_uint4(e[0], e[1], e[2], e[3]);
        }
        #pragma unroll
        for (int i = 0; i < 4; i++){   // y2h: half2 along px -> STG.32
            int e = t + 256*i;          // 0..1023
            int c = e >> 5, pp = e & 31;
            int px = 2*pp;
            __half2 hh = __floats2half2_rn(Tb[(32+c)*66 + px], Tb[(32+c)*66 + px + 1]);
            *reinterpret_cast<__half2*>(&g_y2h[((size_t)b*32 + c)*HWSZ + px0 + px]) = hh;
        }
        #pragma unroll
        for (int i = 0; i < 4; i++){   // y3h: 2 px of one cp -> STG.64
            int e = t + 256*i;          // 0..1023
            int cp = e >> 5, pp = e & 31;
            int px = 2*pp;
            __half2 h0 = __floats2half2_rn(Tb[(64+2*cp)*66 + px],     Tb[(64+2*cp+1)*66 + px]);
            __half2 h1 = __floats2half2_rn(Tb[(64+2*cp)*66 + px + 1], Tb[(64+2*cp+1)*66 + px + 1]);
            uint2 pkt;
            pkt.x = *reinterpret_cast<uint32_t*>(&h0);
            pkt.y = *reinterpret_cast<uint32_t*>(&h1);
            *reinterpret_cast<uint2*>(&g_y3h[((size_t)(b*32 + cp))*HWSZ + px0 + px]) = pkt;
        }
        __syncthreads();
    }
}

// ---------------------------------------------------------------------------
// attn_tiled: EXACT Round-11 version (best known).
// ---------------------------------------------------------------------------
#define PITCH 341
#define HALO  340

__global__ void __launch_bounds__(256) attn_tiled(const float* __restrict__ x,
                                                  const float* __restrict__ gamma,
                                                  float* __restrict__ out){
    __shared__ uint32_t sm1[16*PITCH];
    __shared__ uint32_t sm3[8*PITCH];
    int t = threadIdx.x, lane = t & 31, wi = t >> 5;
    int b = blockIdx.z, h0 = blockIdx.y*8, w0 = blockIdx.x*32;
    size_t pb = (size_t)b << 18;

    {
        const uint32_t* y1v = reinterpret_cast<const uint32_t*>(g_y1h);
        for (int e = t; e < HALO*16; e += 256){
            int hp = e >> 4, cp = e & 15;
            int hr = hp / 34, hc = hp - hr*34;
            int nh = min(max(h0 + hr - 1, 0), 511);
            int nw = min(max(w0 + hc - 1, 0), 511);
            sm1[cp*PITCH + hp] = y1v[(pb + (size_t)((nh<<9) + nw))*16 + cp];
        }
    }
    __syncthreads();

    int hbase = (wi+1)*34 + lane + 1;
    float av[9];
    {
        float acct[9];
        #pragma unroll
        for (int n = 0; n < 9; n++) acct[n] = 0.f;
        const __half* x2p = g_y2h + ((size_t)b*32)*HWSZ + (size_t)(((h0+wi)<<9) + w0 + lane);
        #pragma unroll 4
        for (int cp = 0; cp < 16; cp++){
            float xa = 0.5f * __half2float(__ldg(x2p + (size_t)(2*cp)*HWSZ));
            float xc = 0.5f * __half2float(__ldg(x2p + (size_t)(2*cp+1)*HWSZ));
            #pragma unroll
            for (int n = 0; n < 9; n++){
                const int D = (n/3 - 1)*34 + (n%3 - 1);
                float2 f = __half22float2(*reinterpret_cast<const __half2*>(&sm1[cp*PITCH + hbase + D]));
                float t0, t1;
                asm("tanh.approx.f32 %0, %1;" : "=f"(t0) : "f"(f.x * xa));
                asm("tanh.approx.f32 %0, %1;" : "=f"(t1) : "f"(f.y * xc));
                acct[n] += t0 + t1;
            }
        }
        #pragma unroll
        for (int n = 0; n < 9; n++){
            int nh = h0 + wi + n/3 - 1, nw = w0 + lane + n%3 - 1;
            bool ok = ((unsigned)nh < 512u) && ((unsigned)nw < 512u);
            av[n] = ok ? fmaf(0.5f, acct[n], 16.0f) : 0.f;
        }
    }

    float gm = __ldg(gamma);
    int hw = ((h0+wi)<<9) + w0 + lane;
    #pragma unroll 1
    for (int ch = 0; ch < 4; ch++){
        __syncthreads();
        {
            const uint32_t* src = reinterpret_cast<const uint32_t*>(
                g_y3h + ((size_t)(b*32 + ch*8 + wi))*HWSZ);
            for (int hp = lane; hp < HALO; hp += 32){
                int hr = hp / 34, hc = hp - hr*34;
                int nh = min(max(h0 + hr - 1, 0), 511);
                int nw = min(max(w0 + hc - 1, 0), 511);
                sm3[wi*PITCH + hp] = src[(nh<<9) + nw];
            }
        }
        __syncthreads();
        size_t obase = ((size_t)(b*64 + ch*16))*HWSZ + hw;
        #pragma unroll
        for (int cpl = 0; cpl < 8; cpl++){
            float a0 = 0.f, a1 = 0.f;
            #pragma unroll
            for (int n = 0; n < 9; n++){
                const int D = (n/3 - 1)*34 + (n%3 - 1);
                float2 f = __half22float2(*reinterpret_cast<const __half2*>(&sm3[cpl*PITCH + hbase + D]));
                a0 = fmaf(f.x, av[n], a0);
                a1 = fmaf(f.y, av[n], a1);
            }
            size_t o0 = obase + (size_t)(2*cpl)*HWSZ;
            size_t o1 = o0 + HWSZ;
            out[o0] = x[o0] + gm * a0;
            out[o1] = x[o1] + gm * a1;
        }
    }
}

extern "C" void kernel_launch(void* const* d_in, const int* in_sizes, int n_in,
                              void* d_out, int out_size){
    const float* x     = (const float*)d_in[0];
    const float* w1    = (const float*)d_in[1];
    const float* b1    = (const float*)d_in[2];
    const float* w2    = (const float*)d_in[3];
    const float* b2    = (const float*)d_in[4];
    const float* w3    = (const float*)d_in[5];
    const float* b3    = (const float*)d_in[6];
    const float* gamma = (const float*)d_in[7];
    float* out = (float*)d_out;

    cudaFuncSetAttribute(conv_mma, cudaFuncAttributeMaxDynamicSharedMemorySize, CONV_SMEM);
    pack_weights<<<32, 256>>>(w1, b1, w2, b2, w3, b3);
    conv_mma<<<(BATCH*HWSZ)/128, 256, CONV_SMEM>>>(x);
    attn_tiled<<<dim3(16, 64, BATCH), 256>>>(x, gamma, out);
}